// round 16
// baseline (speedup 1.0000x reference)
#include <cuda_runtime.h>
#include <cuda_fp16.h>
#include <math_constants.h>
#include <cstdint>
#include <cstddef>

#define NROWS   65536
#define HD      1024
#define MT      128
#define NT      128
#define KCH     64                       // two 32k sub-chunks per stage
#define GT      128                      // 4 warps, 64x64 warp tile
#define PITCH   40                       // fp16 elems per smem row (80 B)
#define TILEB   (128 * PITCH * 2)        // 10240 B per sub-tile
#define STAGEB  (4 * TILEB)              // A0 B0 A1 B1 = 40960 B
#define SMEM_G  (2 * STAGEB)             // 81920 B

__device__ __half g_act[2][(size_t)NROWS * HD];
__device__ __half g_wt[3][HD * HD];

// ---------------- helpers ----------------
__device__ __forceinline__ uint32_t smem_u32(const void* p) {
    uint32_t a;
    asm("{ .reg .u64 t; cvta.to.shared.u64 t, %1; cvt.u32.u64 %0, t; }" : "=r"(a) : "l"(p));
    return a;
}
__device__ __forceinline__ void cp16(uint32_t dst, const void* src) {
    asm volatile("cp.async.cg.shared.global [%0], [%1], 16;" :: "r"(dst), "l"(src));
}
__device__ __forceinline__ void ldsm4(uint32_t (&r)[4], uint32_t addr) {
    asm volatile("ldmatrix.sync.aligned.m8n8.x4.shared.b16 {%0,%1,%2,%3}, [%4];"
                 : "=r"(r[0]), "=r"(r[1]), "=r"(r[2]), "=r"(r[3]) : "r"(addr));
}
__device__ __forceinline__ void mma16816(float (&d)[4], const uint32_t (&a)[4],
                                         uint32_t b0, uint32_t b1) {
    asm volatile(
        "mma.sync.aligned.m16n8k16.row.col.f32.f16.f16.f32 "
        "{%0,%1,%2,%3},{%4,%5,%6,%7},{%8,%9},{%0,%1,%2,%3};"
        : "+f"(d[0]), "+f"(d[1]), "+f"(d[2]), "+f"(d[3])
        : "r"(a[0]), "r"(a[1]), "r"(a[2]), "r"(a[3]), "r"(b0), "r"(b1));
}
__device__ __forceinline__ float fast_tanh(float x) {
    float e = __expf(2.0f * x);
    return 1.0f - __fdividef(2.0f, e + 1.0f);
}

// ---------------- weight transpose: g_wt[n][k] (fp16) ----------------
__global__ void prep_weights(const float* __restrict__ W1, const float* __restrict__ W2,
                             const float* __restrict__ W3) {
    __shared__ float t[32][33];
    const float* Ws[3] = {W1, W2, W3};
    const float* W = Ws[blockIdx.z];
    int k0 = blockIdx.x * 32, j0 = blockIdx.y * 32;
    int tx = threadIdx.x, ty = threadIdx.y;
    #pragma unroll
    for (int i = 0; i < 32; i += 8)
        t[ty + i][tx] = W[(size_t)(k0 + ty + i) * HD + j0 + tx];
    __syncthreads();
    #pragma unroll
    for (int i = 0; i < 32; i += 8) {
        size_t o = (size_t)(j0 + ty + i) * HD + k0 + tx;
        g_wt[blockIdx.z][o] = __float2half(t[tx][ty + i]);
    }
}

// ---------------- layer 0 + out init ----------------
__global__ __launch_bounds__(256) void layer0_kernel(const float* __restrict__ X,
        const float* __restrict__ W0, const float* __restrict__ b0,
        float* __restrict__ out, const float* __restrict__ bl) {
    __shared__ float xs[64];
    int r0 = blockIdx.x * 32;
    int tid = threadIdx.x;
    if (tid < 64) {
        float v = X[(size_t)r0 * 2 + tid];
        xs[tid] = (tid & 1) ? (v * 2.0f - 1.0f) : (v * (1.0f / CUDART_PI_F) - 1.0f);
    }
    if (tid < 32) out[r0 + tid] = bl[0];     // init output with bias
    __syncthreads();
    int j = tid * 4;
    float wa[4], wb[4], bj[4];
    #pragma unroll
    for (int c = 0; c < 4; c++) { wa[c] = W0[j + c]; wb[c] = W0[HD + j + c]; bj[c] = b0[j + c]; }
    for (int r = 0; r < 32; r++) {
        float xa = xs[2 * r], xb = xs[2 * r + 1];
        __half ph[4];
        #pragma unroll
        for (int c = 0; c < 4; c++)
            ph[c] = __float2half(fast_tanh(fmaf(xa, wa[c], fmaf(xb, wb[c], bj[c]))));
        size_t o = (size_t)(r0 + r) * HD + j;
        *(uint2*)(g_act[0] + o) = *(uint2*)ph;
    }
}

// ---------------- GEMM layer (fp16, 64x64 warp tile, KCH=64, 2-stage) ----------------
__global__ __launch_bounds__(GT, 2)
void gemm_layer(int src, int wsel, const float* __restrict__ bias, int kblk,
                int fuse_final, const float* __restrict__ wl, float* __restrict__ out) {
    extern __shared__ __align__(16) char smem[];
    __shared__ float bias_s[NT];
    __shared__ float wl_s[NT];

    const int tid = threadIdx.x;
    const int n0 = blockIdx.x * NT;
    const int r0 = blockIdx.y * MT;
    const int kb = (n0 / kblk) * kblk;       // block-diagonal k-window
    const int nch = kblk / KCH;              // 16 / 8 / 4
    const int dst = 1 - src;

    if (tid < NT) {
        bias_s[tid] = bias[n0 + tid];
        if (fuse_final) wl_s[tid] = wl[n0 + tid];
    }

    const char* gsrc[2];
    gsrc[0] = (const char*)(g_act[src] + (size_t)r0 * HD + kb);
    gsrc[1] = (const char*)(g_wt[wsel] + (size_t)n0 * HD + kb);

    const uint32_t sb = smem_u32(smem);
    const int lane = tid & 31;
    const int warp = tid >> 5;
    const int mwarp = (warp & 1) * 64;       // 2 warps along M, 64 rows each
    const int nwarp = (warp >> 1) * 64;      // 2 warps along N, 64 cols each

    // ldmatrix per-lane byte offsets (pitch 80 B)
    const int arow = lane & 7, atile = lane >> 3;
    const uint32_t a_loff = (uint32_t)((arow + (atile & 1) * 8) * 80 + (atile >> 1) * 16);
    const uint32_t b_loff = (uint32_t)(((lane & 7) + (atile >> 1) * 8) * 80 + (atile & 1) * 16);

    float acc[4][8][4];
    #pragma unroll
    for (int i = 0; i < 4; i++)
        #pragma unroll
        for (int j = 0; j < 8; j++)
            #pragma unroll
            for (int q = 0; q < 4; q++) acc[i][j][q] = 0.0f;

    // ---- async load of one 64k chunk: [A0 B0 A1 B1], 2048 cp16 / 128 thr = 16 each
    #define LOAD_CHUNK(ch)                                                        \
    {                                                                             \
        uint32_t st_ = sb + (uint32_t)((ch) & 1) * STAGEB;                        \
        size_t ko_ = (size_t)(ch) * (KCH * 2);                                    \
        _Pragma("unroll")                                                         \
        for (int t = 0; t < 16; t++) {                                            \
            int s = tid + t * GT;                                                 \
            int part = s >> 9;          /* 0..3 = A0 B0 A1 B1 */                  \
            int w = s & 511;                                                      \
            int row = w >> 2, seg = w & 3;                                        \
            int tile = part & 1, sub = part >> 1;                                 \
            cp16(st_ + (uint32_t)(part * TILEB + row * 80 + seg * 16),            \
                 gsrc[tile] + (size_t)row * (HD * 2) + ko_ + sub * 64 + seg * 16);\
        }                                                                         \
        asm volatile("cp.async.commit_group;" ::: "memory");                      \
    }

    // prologue: chunk 0 loaded and published
    LOAD_CHUNK(0);
    asm volatile("cp.async.wait_group 0;" ::: "memory");
    __syncthreads();

    for (int c = 0; c < nch; c++) {
        if (c + 1 < nch) LOAD_CHUNK(c + 1);

        uint32_t st0 = sb + (uint32_t)(c & 1) * STAGEB;
        #pragma unroll
        for (int sub = 0; sub < 2; sub++) {
            uint32_t st = st0 + (uint32_t)(sub * 2 * TILEB);
            #pragma unroll
            for (int ks = 0; ks < 2; ks++) {
                const uint32_t kboff = (uint32_t)(ks * 32);
                uint32_t ah[4][4];
                #pragma unroll
                for (int mf = 0; mf < 4; mf++) {
                    uint32_t base = st + (uint32_t)((mwarp + mf * 16) * 80) + kboff;
                    ldsm4(ah[mf], base + 0 * TILEB + a_loff);
                }
                #pragma unroll
                for (int np = 0; np < 4; np++) {
                    uint32_t base = st + (uint32_t)((nwarp + np * 16) * 80) + kboff;
                    uint32_t bh[4];
                    ldsm4(bh, base + 1 * TILEB + b_loff);
                    #pragma unroll
                    for (int h = 0; h < 2; h++)
                        #pragma unroll
                        for (int mf = 0; mf < 4; mf++)
                            mma16816(acc[mf][np * 2 + h], ah[mf],
                                     bh[2 * h], bh[2 * h + 1]);
                }
            }
        }

        if (c + 1 < nch) {
            asm volatile("cp.async.wait_group 0;" ::: "memory");
            __syncthreads();
        }
    }
    #undef LOAD_CHUNK

    const int cL = nwarp + (lane & 3) * 2;    // local col of c0 within warp nf=0

    if (fuse_final) {
        // ---- fused output layer: tanh -> dot with Wl -> atomicAdd ----
        #pragma unroll
        for (int mf = 0; mf < 4; mf++) {
            int rtop = r0 + mwarp + mf * 16 + (lane >> 2);
            #pragma unroll
            for (int half = 0; half < 2; half++) {
                int row = rtop + half * 8;
                float s = 0.0f;
                #pragma unroll
                for (int nf = 0; nf < 8; nf++) {
                    int col = cL + nf * 8;
                    float v0 = fast_tanh(acc[mf][nf][2 * half]     + bias_s[col]);
                    float v1 = fast_tanh(acc[mf][nf][2 * half + 1] + bias_s[col + 1]);
                    s = fmaf(v0, wl_s[col], fmaf(v1, wl_s[col + 1], s));
                }
                atomicAdd(out + row, s);
            }
        }
        return;
    }

    // ---- epilogue: bias + tanh, write fp16 ----
    #pragma unroll
    for (int mf = 0; mf < 4; mf++) {
        int rtop = r0 + mwarp + mf * 16 + (lane >> 2);
        #pragma unroll
        for (int half = 0; half < 2; half++) {
            int row = rtop + half * 8;
            __half* oh = g_act[dst] + (size_t)row * HD + n0;
            #pragma unroll
            for (int nf = 0; nf < 8; nf++) {
                int col = cL + nf * 8;
                float v0 = fast_tanh(acc[mf][nf][2 * half]     + bias_s[col]);
                float v1 = fast_tanh(acc[mf][nf][2 * half + 1] + bias_s[col + 1]);
                __half2 ph; ph.x = __float2half(v0); ph.y = __float2half(v1);
                *(__half2*)(oh + col) = ph;
            }
        }
    }
}

// ---------------- launcher ----------------
extern "C" void kernel_launch(void* const* d_in, const int* in_sizes, int n_in,
                              void* d_out, int out_size)
{
    const float* X  = (const float*)d_in[0];
    const float* W0 = (const float*)d_in[1];
    const float* b0 = (const float*)d_in[2];
    const float* W1 = (const float*)d_in[3];
    const float* b1 = (const float*)d_in[4];
    const float* W2 = (const float*)d_in[5];
    const float* b2 = (const float*)d_in[6];
    const float* W3 = (const float*)d_in[7];
    const float* b3 = (const float*)d_in[8];
    const float* Wl = (const float*)d_in[9];
    const float* bl = (const float*)d_in[10];
    float* out = (float*)d_out;

    cudaFuncSetAttribute(gemm_layer, cudaFuncAttributeMaxDynamicSharedMemorySize, SMEM_G);

    prep_weights<<<dim3(32, 32, 3), dim3(32, 8)>>>(W1, W2, W3);
    layer0_kernel<<<NROWS / 32, 256>>>(X, W0, b0, out, bl);
    gemm_layer<<<dim3(HD / NT, NROWS / MT), GT, SMEM_G>>>(0, 0, b1, 1024, 0, nullptr, nullptr);
    gemm_layer<<<dim3(HD / NT, NROWS / MT), GT, SMEM_G>>>(1, 1, b2, 512, 0, nullptr, nullptr);
    gemm_layer<<<dim3(HD / NT, NROWS / MT), GT, SMEM_G>>>(0, 2, b3, 256, 1, Wl, out);
}

// round 17
// speedup vs baseline: 1.1022x; 1.1022x over previous
#include <cuda_runtime.h>
#include <cuda_fp16.h>
#include <math_constants.h>
#include <cstdint>
#include <cstddef>

#define NROWS   65536
#define HD      1024
#define MT      128
#define NT      128
#define KCH     32
#define GT      128                      // 4 warps, 64x64 warp tile
#define PITCH   40                       // fp16 elems per smem row (80 B)
#define TILEB   (128 * PITCH * 2)        // 10240 B per tile
#define STAGEB  (2 * TILEB)              // A B = 20480 B
#define NSTAGE  3
#define SMEM_G  (NSTAGE * STAGEB)        // 61440 B

__device__ __half g_act[2][(size_t)NROWS * HD];
__device__ __half g_wt[3][HD * HD];

// ---------------- helpers ----------------
__device__ __forceinline__ uint32_t smem_u32(const void* p) {
    uint32_t a;
    asm("{ .reg .u64 t; cvta.to.shared.u64 t, %1; cvt.u32.u64 %0, t; }" : "=r"(a) : "l"(p));
    return a;
}
__device__ __forceinline__ void cp16(uint32_t dst, const void* src) {
    asm volatile("cp.async.cg.shared.global [%0], [%1], 16;" :: "r"(dst), "l"(src));
}
__device__ __forceinline__ void ldsm4(uint32_t (&r)[4], uint32_t addr) {
    asm volatile("ldmatrix.sync.aligned.m8n8.x4.shared.b16 {%0,%1,%2,%3}, [%4];"
                 : "=r"(r[0]), "=r"(r[1]), "=r"(r[2]), "=r"(r[3]) : "r"(addr));
}
__device__ __forceinline__ void mma16816(float (&d)[4], const uint32_t (&a)[4],
                                         uint32_t b0, uint32_t b1) {
    asm volatile(
        "mma.sync.aligned.m16n8k16.row.col.f32.f16.f16.f32 "
        "{%0,%1,%2,%3},{%4,%5,%6,%7},{%8,%9},{%0,%1,%2,%3};"
        : "+f"(d[0]), "+f"(d[1]), "+f"(d[2]), "+f"(d[3])
        : "r"(a[0]), "r"(a[1]), "r"(a[2]), "r"(a[3]), "r"(b0), "r"(b1));
}
__device__ __forceinline__ float fast_tanh(float x) {
    float e = __expf(2.0f * x);
    return 1.0f - __fdividef(2.0f, e + 1.0f);
}

// ---------------- weight transpose: g_wt[n][k] (fp16) ----------------
__global__ void prep_weights(const float* __restrict__ W1, const float* __restrict__ W2,
                             const float* __restrict__ W3) {
    __shared__ float t[32][33];
    const float* Ws[3] = {W1, W2, W3};
    const float* W = Ws[blockIdx.z];
    int k0 = blockIdx.x * 32, j0 = blockIdx.y * 32;
    int tx = threadIdx.x, ty = threadIdx.y;
    #pragma unroll
    for (int i = 0; i < 32; i += 8)
        t[ty + i][tx] = W[(size_t)(k0 + ty + i) * HD + j0 + tx];
    __syncthreads();
    #pragma unroll
    for (int i = 0; i < 32; i += 8) {
        size_t o = (size_t)(j0 + ty + i) * HD + k0 + tx;
        g_wt[blockIdx.z][o] = __float2half(t[tx][ty + i]);
    }
}

// ---------------- layer 0 + out init ----------------
__global__ __launch_bounds__(256) void layer0_kernel(const float* __restrict__ X,
        const float* __restrict__ W0, const float* __restrict__ b0,
        float* __restrict__ out, const float* __restrict__ bl) {
    __shared__ float xs[64];
    int r0 = blockIdx.x * 32;
    int tid = threadIdx.x;
    if (tid < 64) {
        float v = X[(size_t)r0 * 2 + tid];
        xs[tid] = (tid & 1) ? (v * 2.0f - 1.0f) : (v * (1.0f / CUDART_PI_F) - 1.0f);
    }
    if (tid < 32) out[r0 + tid] = bl[0];     // init output with bias
    __syncthreads();
    int j = tid * 4;
    float wa[4], wb[4], bj[4];
    #pragma unroll
    for (int c = 0; c < 4; c++) { wa[c] = W0[j + c]; wb[c] = W0[HD + j + c]; bj[c] = b0[j + c]; }
    for (int r = 0; r < 32; r++) {
        float xa = xs[2 * r], xb = xs[2 * r + 1];
        __half ph[4];
        #pragma unroll
        for (int c = 0; c < 4; c++)
            ph[c] = __float2half(fast_tanh(fmaf(xa, wa[c], fmaf(xb, wb[c], bj[c]))));
        size_t o = (size_t)(r0 + r) * HD + j;
        *(uint2*)(g_act[0] + o) = *(uint2*)ph;
    }
}

// ---------------- GEMM layer (fp16, 64x64 warp tile, 3-stage, batched LDSM) ----------------
__global__ __launch_bounds__(GT, 2)
void gemm_layer(int src, int wsel, const float* __restrict__ bias, int kblk,
                int fuse_final, const float* __restrict__ wl, float* __restrict__ out) {
    extern __shared__ __align__(16) char smem[];
    __shared__ float bias_s[NT];
    __shared__ float wl_s[NT];

    const int tid = threadIdx.x;
    const int n0 = blockIdx.x * NT;
    const int r0 = blockIdx.y * MT;
    const int kb = (n0 / kblk) * kblk;       // block-diagonal k-window
    const int nch = kblk / KCH;              // 32 / 16 / 8
    const int dst = 1 - src;

    if (tid < NT) {
        bias_s[tid] = bias[n0 + tid];
        if (fuse_final) wl_s[tid] = wl[n0 + tid];
    }

    const char* gsrc[2];
    gsrc[0] = (const char*)(g_act[src] + (size_t)r0 * HD + kb);
    gsrc[1] = (const char*)(g_wt[wsel] + (size_t)n0 * HD + kb);

    const uint32_t sb = smem_u32(smem);
    const int lane = tid & 31;
    const int warp = tid >> 5;
    const int mwarp = (warp & 1) * 64;       // 2 warps along M, 64 rows each
    const int nwarp = (warp >> 1) * 64;      // 2 warps along N, 64 cols each

    // ldmatrix per-lane byte offsets (pitch 80 B)
    const int arow = lane & 7, atile = lane >> 3;
    const uint32_t a_loff = (uint32_t)((arow + (atile & 1) * 8) * 80 + (atile >> 1) * 16);
    const uint32_t b_loff = (uint32_t)(((lane & 7) + (atile >> 1) * 8) * 80 + (atile & 1) * 16);

    float acc[4][8][4];
    #pragma unroll
    for (int i = 0; i < 4; i++)
        #pragma unroll
        for (int j = 0; j < 8; j++)
            #pragma unroll
            for (int q = 0; q < 4; q++) acc[i][j][q] = 0.0f;

    // ---- async load of one K-chunk (2 tiles, 1024 cp16 / 128 thr = 8 each) ----
    #define LOAD_CHUNK(ch)                                                        \
    {                                                                             \
        uint32_t st_ = sb + (uint32_t)((ch) % NSTAGE) * STAGEB;                   \
        size_t ko_ = (size_t)(ch) * (KCH * 2);                                    \
        _Pragma("unroll")                                                         \
        for (int t = 0; t < 8; t++) {                                             \
            int s = tid + t * GT;                                                 \
            int tile = s >> 9, w = s & 511;                                       \
            int row = w >> 2, seg = w & 3;                                        \
            cp16(st_ + (uint32_t)(tile * TILEB + row * 80 + seg * 16),            \
                 gsrc[tile] + (size_t)row * (HD * 2) + ko_ + seg * 16);           \
        }                                                                         \
        asm volatile("cp.async.commit_group;" ::: "memory");                      \
    }

    // prologue: 2 chunks in flight (nch >= 8 always)
    LOAD_CHUNK(0);
    LOAD_CHUNK(1);

    for (int c = 0; c < nch; c++) {
        // one commit per iteration => wait_group 1 certifies chunk c
        asm volatile("cp.async.wait_group 1;" ::: "memory");
        __syncthreads();     // retires iter c-1 LDSMs before buf (c+2)%3 reuse
        if (c + 2 < nch) {
            LOAD_CHUNK(c + 2);
        } else {
            asm volatile("cp.async.commit_group;" ::: "memory");  // uniform count
        }

        uint32_t st = sb + (uint32_t)(c % NSTAGE) * STAGEB;

        // ---- phase 1: issue ALL 16 LDSMs for the 64-k chunk ----
        uint32_t ah[2][4][4];     // [ks][mf][4]
        uint32_t bh[2][4][4];     // [ks][np][4]
        #pragma unroll
        for (int ks = 0; ks < 2; ks++) {
            const uint32_t kboff = (uint32_t)(ks * 32);
            #pragma unroll
            for (int mf = 0; mf < 4; mf++) {
                uint32_t base = st + (uint32_t)((mwarp + mf * 16) * 80) + kboff;
                ldsm4(ah[ks][mf], base + 0 * TILEB + a_loff);
            }
            #pragma unroll
            for (int np = 0; np < 4; np++) {
                uint32_t base = st + (uint32_t)((nwarp + np * 16) * 80) + kboff;
                ldsm4(bh[ks][np], base + 1 * TILEB + b_loff);
            }
        }

        // ---- phase 2: 64 back-to-back MMAs ----
        #pragma unroll
        for (int ks = 0; ks < 2; ks++)
            #pragma unroll
            for (int np = 0; np < 4; np++)
                #pragma unroll
                for (int h = 0; h < 2; h++)
                    #pragma unroll
                    for (int mf = 0; mf < 4; mf++)
                        mma16816(acc[mf][np * 2 + h], ah[ks][mf],
                                 bh[ks][np][2 * h], bh[ks][np][2 * h + 1]);
    }
    #undef LOAD_CHUNK

    const int cL = nwarp + (lane & 3) * 2;    // local col of c0 within warp nf=0

    if (fuse_final) {
        // ---- fused output layer: tanh -> dot with Wl -> atomicAdd ----
        #pragma unroll
        for (int mf = 0; mf < 4; mf++) {
            int rtop = r0 + mwarp + mf * 16 + (lane >> 2);
            #pragma unroll
            for (int half = 0; half < 2; half++) {
                int row = rtop + half * 8;
                float s = 0.0f;
                #pragma unroll
                for (int nf = 0; nf < 8; nf++) {
                    int col = cL + nf * 8;
                    float v0 = fast_tanh(acc[mf][nf][2 * half]     + bias_s[col]);
                    float v1 = fast_tanh(acc[mf][nf][2 * half + 1] + bias_s[col + 1]);
                    s = fmaf(v0, wl_s[col], fmaf(v1, wl_s[col + 1], s));
                }
                atomicAdd(out + row, s);
            }
        }
        return;
    }

    // ---- epilogue: bias + tanh, write fp16 ----
    #pragma unroll
    for (int mf = 0; mf < 4; mf++) {
        int rtop = r0 + mwarp + mf * 16 + (lane >> 2);
        #pragma unroll
        for (int half = 0; half < 2; half++) {
            int row = rtop + half * 8;
            __half* oh = g_act[dst] + (size_t)row * HD + n0;
            #pragma unroll
            for (int nf = 0; nf < 8; nf++) {
                int col = cL + nf * 8;
                float v0 = fast_tanh(acc[mf][nf][2 * half]     + bias_s[col]);
                float v1 = fast_tanh(acc[mf][nf][2 * half + 1] + bias_s[col + 1]);
                __half2 ph; ph.x = __float2half(v0); ph.y = __float2half(v1);
                *(__half2*)(oh + col) = ph;
            }
        }
    }
}

// ---------------- launcher ----------------
extern "C" void kernel_launch(void* const* d_in, const int* in_sizes, int n_in,
                              void* d_out, int out_size)
{
    const float* X  = (const float*)d_in[0];
    const float* W0 = (const float*)d_in[1];
    const float* b0 = (const float*)d_in[2];
    const float* W1 = (const float*)d_in[3];
    const float* b1 = (const float*)d_in[4];
    const float* W2 = (const float*)d_in[5];
    const float* b2 = (const float*)d_in[6];
    const float* W3 = (const float*)d_in[7];
    const float* b3 = (const float*)d_in[8];
    const float* Wl = (const float*)d_in[9];
    const float* bl = (const float*)d_in[10];
    float* out = (float*)d_out;

    cudaFuncSetAttribute(gemm_layer, cudaFuncAttributeMaxDynamicSharedMemorySize, SMEM_G);

    prep_weights<<<dim3(32, 32, 3), dim3(32, 8)>>>(W1, W2, W3);
    layer0_kernel<<<NROWS / 32, 256>>>(X, W0, b0, out, bl);
    gemm_layer<<<dim3(HD / NT, NROWS / MT), GT, SMEM_G>>>(0, 0, b1, 1024, 0, nullptr, nullptr);
    gemm_layer<<<dim3(HD / NT, NROWS / MT), GT, SMEM_G>>>(1, 1, b2, 512, 0, nullptr, nullptr);
    gemm_layer<<<dim3(HD / NT, NROWS / MT), GT, SMEM_G>>>(0, 2, b3, 256, 1, Wl, out);
}